// round 16
// baseline (speedup 1.0000x reference)
#include <cuda_runtime.h>
#include <cuda_bf16.h>
#include <stdint.h>
#include <math.h>

#define B_DIM 8
#define Q_DIM 64
#define N_DIM 8192
#define K_DIM 512
#define C_DIM 256

#define GRID 304               // persistent CTAs, 2 per SM
#define THREADS 128
#define N_TP 512               // transpose items (one per 128-n pair)
#define N_VQ_PAIRS 512         // 128 n-columns each
#define N_REC 512              // 128 n-columns each
#define N_WORK (N_TP + N_VQ_PAIRS + N_REC)   // 1536
#define NP (N_VQ_PAIRS + N_REC)              // 1024 partial slots

__device__ float g_partials[NP];
__device__ int   g_arrived;
__device__ int   g_work;
__device__ int   g_ready[N_TP];                                   // zero-init
__device__ __align__(16) __nv_bfloat16 g_zeT[B_DIM * N_DIM * Q_DIM]; // 8 MB
__device__ float g_ze2[B_DIM * N_DIM];

// ---------------- smem layout (bytes) ----------------
#define SM_E2    0             // 2048B (||emb_k||^2)
#define SM_WMIN  2048          // 2048B ([4 warps][128 n])
#define SM_RED   4096          // 32B
#define SM_ZET   4224          // 2 x 16384B zeT bf16 buffers (swizzled)
#define SM_EMB   36992         // 65536B (emb bf16, swizzled)
#define SMEM_TOTAL 102528      // ~100 KB -> 2 CTAs/SM

// ---------------- helpers ----------------
__device__ __forceinline__ uint32_t smem_u32(const void* p) {
    uint32_t a;
    asm("{ .reg .u64 t; cvta.to.shared.u64 t, %1; cvt.u32.u64 %0, t; }" : "=r"(a) : "l"(p));
    return a;
}
__device__ __forceinline__ int ld_acq(const int* p) {
    int v;
    asm volatile("ld.acquire.gpu.global.b32 %0, [%1];" : "=r"(v) : "l"(p) : "memory");
    return v;
}

#define LDSM_X4(r0, r1, r2, r3, addr) \
    asm volatile("ldmatrix.sync.aligned.m8n8.x4.shared.b16 {%0,%1,%2,%3}, [%4];" \
                 : "=r"(r0), "=r"(r1), "=r"(r2), "=r"(r3) : "r"(addr))

#define MMA_BF16(a0, a1, a2, a3, b0, b1, c0, c1, c2, c3) \
    asm volatile("mma.sync.aligned.m16n8k16.row.col.f32.bf16.bf16.f32 " \
                 "{%0,%1,%2,%3}, {%4,%5,%6,%7}, {%8,%9}, {%0,%1,%2,%3};" \
                 : "+f"(c0), "+f"(c1), "+f"(c2), "+f"(c3) \
                 : "r"(a0), "r"(a1), "r"(a2), "r"(a3), "r"(b0), "r"(b1))

#define CP_ASYNC16(saddr, gptr) \
    asm volatile("cp.async.cg.shared.global [%0], [%1], 16;" \
                 :: "r"(saddr), "l"(gptr) : "memory")
#define CP_COMMIT() asm volatile("cp.async.commit_group;" ::: "memory")
#define CP_WAIT(n)  asm volatile("cp.async.wait_group %0;" :: "n"(n) : "memory")

// work-id decoding: [0,512) transpose; then even = vq pair, odd = rec tile
__device__ __forceinline__ bool is_vq(int id) {
    return id >= N_TP && (((id - N_TP) & 1) == 0);
}
__device__ __forceinline__ int sub_id(int id) { return (id - N_TP) >> 1; }

// Last-arriving block sums all partials in a FIXED order -> bit-deterministic.
__device__ __forceinline__ void finalize(float* out) {
    __shared__ float fr[4];
    __shared__ int last;
    __threadfence();
    if (threadIdx.x == 0)
        last = (atomicAdd(&g_arrived, 1) == GRID - 1);
    __syncthreads();
    if (!last) return;
    __threadfence();
    float s = 0.0f;
    for (int i = threadIdx.x; i < NP; i += THREADS)
        s += g_partials[i];
    #pragma unroll
    for (int off = 16; off > 0; off >>= 1)
        s += __shfl_down_sync(0xFFFFFFFFu, s, off);
    if ((threadIdx.x & 31) == 0) fr[threadIdx.x >> 5] = s;
    __syncthreads();
    if (threadIdx.x == 0) {
        out[0] = ((fr[0] + fr[1]) + (fr[2] + fr[3]));
        g_arrived = 0;
        g_work = 0;
    }
    // reset ready flags for next graph replay
    for (int i = threadIdx.x; i < N_TP; i += THREADS) g_ready[i] = 0;
}

// cp.async one pre-transposed bf16 pair (16 KB) into swizzled smem.
__device__ __forceinline__ void cp_pair(int pair, uint32_t dst, int tid) {
    const char* src = (const char*)g_zeT + (size_t)pair * 16384;
    #pragma unroll
    for (int i = 0; i < 8; i++) {
        int c = tid + 128 * i;            // 0..1023 16B chunks
        int r = c >> 3, j = c & 7;
        CP_ASYNC16(dst + (uint32_t)(r * 128 + ((j ^ (r & 7)) * 16)), src + c * 16);
    }
    CP_COMMIT();
}

// ==================== fused persistent kernel ====================
__global__ __launch_bounds__(THREADS, 2) void fused_kernel(
    const float* __restrict__ ze, const float* __restrict__ emb,
    const float* __restrict__ qp, const int* __restrict__ tw,
    float* __restrict__ out)
{
    extern __shared__ char smem[];
    __shared__ int sh_next, sh_nok;
    const uint32_t sb = smem_u32(smem);
    const int tid  = threadIdx.x;
    const int lane = tid & 31;
    const int wid  = tid >> 5;

    float* wmin = (float*)(smem + SM_WMIN);
    float* red  = (float*)(smem + SM_RED);

    // ---- one-time: emb fp32 -> bf16 swizzled smem + ||emb||^2 ----
    {
        float* e2 = (float*)(smem + SM_E2);
        #pragma unroll
        for (int i = 0; i < K_DIM / THREADS; i++) {
            int k = tid + THREADS * i;
            const float4* src = (const float4*)(emb + (size_t)k * Q_DIM);
            char* dst = smem + SM_EMB + k * 128;
            const int kx = k & 7;
            float s = 0.0f;
            #pragma unroll
            for (int j = 0; j < 8; j++) {
                float4 v0 = src[2 * j];
                float4 v1 = src[2 * j + 1];
                s = fmaf(v0.x, v0.x, s); s = fmaf(v0.y, v0.y, s);
                s = fmaf(v0.z, v0.z, s); s = fmaf(v0.w, v0.w, s);
                s = fmaf(v1.x, v1.x, s); s = fmaf(v1.y, v1.y, s);
                s = fmaf(v1.z, v1.z, s); s = fmaf(v1.w, v1.w, s);
                __nv_bfloat162 p0 = __floats2bfloat162_rn(v0.x, v0.y);
                __nv_bfloat162 p1 = __floats2bfloat162_rn(v0.z, v0.w);
                __nv_bfloat162 p2 = __floats2bfloat162_rn(v1.x, v1.y);
                __nv_bfloat162 p3 = __floats2bfloat162_rn(v1.z, v1.w);
                uint4 u;
                u.x = *(uint32_t*)&p0; u.y = *(uint32_t*)&p1;
                u.z = *(uint32_t*)&p2; u.w = *(uint32_t*)&p3;
                *(uint4*)(dst + ((j ^ kx) * 16)) = u;
            }
            e2[k] = s;
        }
    }

    const float* e2s = (const float*)(smem + SM_E2);

    // swizzled loop-invariant ldmatrix lane offsets (buffer base added at use)
    uint32_t aoff[4];
    #pragma unroll
    for (int ks = 0; ks < 4; ks++)
        aoff[ks] = (uint32_t)(lane & 15) * 128u
                 + (uint32_t)((((lane >> 4) + 2 * ks) ^ (lane & 7)) * 16);
    const uint32_t baddr0 = sb + SM_EMB + (uint32_t)(128 * wid + (lane & 7)) * 128u
                          + (uint32_t)(((lane >> 3) ^ (lane & 7)) * 16);
    const uint32_t baddr1 = sb + SM_EMB + (uint32_t)(128 * wid + (lane & 7)) * 128u
                          + (uint32_t)((((lane >> 3) + 4) ^ (lane & 7)) * 16);

    if (tid == 0) sh_next = atomicAdd(&g_work, 1);
    __syncthreads();
    int cur  = sh_next;
    int pend = -1;       // vq item whose cp.async data is in buffer pbuf
    int pbuf = 0;

    while (cur < N_WORK) {
        const bool curvq = is_vq(cur);

        // ensure cur's data is issued (spin on producer flag if needed)
        if (curvq && pend != cur) {
            if (tid == 0)
                while (!ld_acq(&g_ready[sub_id(cur)])) __nanosleep(64);
            __syncthreads();
            cp_pair(sub_id(cur), sb + SM_ZET + (uint32_t)pbuf * 16384u, tid);
            pend = cur;
        }

        // claim next; probe its readiness (non-blocking)
        if (tid == 0) {
            int nx = atomicAdd(&g_work, 1);
            sh_next = nx;
            sh_nok = (nx < N_WORK && is_vq(nx)) ? ld_acq(&g_ready[sub_id(nx)]) : 0;
        }
        __syncthreads();
        const int next = sh_next;
        const int nok  = sh_nok;
        int nb = pbuf;
        if (nok) {                         // prefetch next vq pair
            nb = (pend >= 0) ? (pbuf ^ 1) : pbuf;
            cp_pair(sub_id(next), sb + SM_ZET + (uint32_t)nb * 16384u, tid);
        }

        if (cur < N_TP) {
            // ================= TRANSPOSE item (pair 'cur') =================
            const int p  = cur;
            const int b  = p >> 6;
            const int n0 = (p & 63) << 7;
            const int c  = tid;
            const float* zc = ze + (size_t)b * Q_DIM * N_DIM + n0 + c;
            uint4* dst = (uint4*)((char*)g_zeT + (size_t)p * 16384 + (size_t)c * 128);
            float z2 = 0.0f;
            #pragma unroll
            for (int h = 0; h < 8; h++) {
                float x0 = zc[(size_t)(8 * h + 0) * N_DIM];
                float x1 = zc[(size_t)(8 * h + 1) * N_DIM];
                float x2 = zc[(size_t)(8 * h + 2) * N_DIM];
                float x3 = zc[(size_t)(8 * h + 3) * N_DIM];
                float x4 = zc[(size_t)(8 * h + 4) * N_DIM];
                float x5 = zc[(size_t)(8 * h + 5) * N_DIM];
                float x6 = zc[(size_t)(8 * h + 6) * N_DIM];
                float x7 = zc[(size_t)(8 * h + 7) * N_DIM];
                z2 = fmaf(x0, x0, z2); z2 = fmaf(x1, x1, z2);
                z2 = fmaf(x2, x2, z2); z2 = fmaf(x3, x3, z2);
                z2 = fmaf(x4, x4, z2); z2 = fmaf(x5, x5, z2);
                z2 = fmaf(x6, x6, z2); z2 = fmaf(x7, x7, z2);
                __nv_bfloat162 p0 = __floats2bfloat162_rn(x0, x1);
                __nv_bfloat162 p1 = __floats2bfloat162_rn(x2, x3);
                __nv_bfloat162 p2 = __floats2bfloat162_rn(x4, x5);
                __nv_bfloat162 p3 = __floats2bfloat162_rn(x6, x7);
                uint4 u;
                u.x = *(uint32_t*)&p0; u.y = *(uint32_t*)&p1;
                u.z = *(uint32_t*)&p2; u.w = *(uint32_t*)&p3;
                dst[h] = u;
            }
            g_ze2[p * 128 + c] = z2;
            __syncthreads();
            if (tid == 0) {
                __threadfence();
                atomicExch(&g_ready[p], 1);   // release-publish
            }
        } else if (curvq) {
            // ================= VQ pair (128 n-columns) =================
            const int pair = sub_id(cur);
            CP_WAIT(1);                       // if nok: leave next pending
            if (!nok) CP_WAIT(0);
            __syncthreads();
            const uint32_t abase = sb + SM_ZET + (uint32_t)pbuf * 16384u;

            // ---- ALL 8 A-sets (128 n-rows) into registers ----
            uint32_t a[8][4][4];
            #pragma unroll
            for (int s = 0; s < 8; s++) {
                #pragma unroll
                for (int ks = 0; ks < 4; ks++)
                    LDSM_X4(a[s][ks][0], a[s][ks][1], a[s][ks][2], a[s][ks][3],
                            abase + aoff[ks] + (uint32_t)s * 2048u);
            }

            float vmin[8][2];
            #pragma unroll
            for (int s = 0; s < 8; s++) { vmin[s][0] = 3.4e38f; vmin[s][1] = 3.4e38f; }

            // ---- stream B once: 16 groups x (2 LDSM.x4 + 32 MMAs) ----
            #pragma unroll 2
            for (int ct = 0; ct < 16; ct++) {
                uint32_t bb[8];
                LDSM_X4(bb[0], bb[1], bb[2], bb[3], baddr0 + (uint32_t)ct * 1024u);
                LDSM_X4(bb[4], bb[5], bb[6], bb[7], baddr1 + (uint32_t)ct * 1024u);
                float2 e2 = *(const float2*)(e2s + 128 * wid + ct * 8 + 2 * (lane & 3));
                #pragma unroll
                for (int s = 0; s < 8; s++) {
                    float e0 = 0.f, e1 = 0.f, er2 = 0.f, e3 = 0.f;
                    float o0 = 0.f, o1 = 0.f, o2 = 0.f, o3 = 0.f;
                    MMA_BF16(a[s][0][0], a[s][0][1], a[s][0][2], a[s][0][3], bb[0], bb[1], e0, e1, er2, e3);
                    MMA_BF16(a[s][1][0], a[s][1][1], a[s][1][2], a[s][1][3], bb[2], bb[3], o0, o1, o2, o3);
                    MMA_BF16(a[s][2][0], a[s][2][1], a[s][2][2], a[s][2][3], bb[4], bb[5], e0, e1, er2, e3);
                    MMA_BF16(a[s][3][0], a[s][3][1], a[s][3][2], a[s][3][3], bb[6], bb[7], o0, o1, o2, o3);
                    float c0 = e0 + o0, c1 = e1 + o1, c2 = er2 + o2, c3 = e3 + o3;
                    vmin[s][0] = fminf(vmin[s][0],
                                       fminf(fmaf(-2.0f, c0, e2.x), fmaf(-2.0f, c1, e2.y)));
                    vmin[s][1] = fminf(vmin[s][1],
                                       fminf(fmaf(-2.0f, c2, e2.x), fmaf(-2.0f, c3, e2.y)));
                }
            }

            // min across the 4 lanes of each row-quad
            #pragma unroll
            for (int s = 0; s < 8; s++) {
                #pragma unroll
                for (int h = 0; h < 2; h++) {
                    vmin[s][h] = fminf(vmin[s][h], __shfl_xor_sync(0xFFFFFFFFu, vmin[s][h], 1));
                    vmin[s][h] = fminf(vmin[s][h], __shfl_xor_sync(0xFFFFFFFFu, vmin[s][h], 2));
                }
            }
            if ((lane & 3) == 0) {
                int rr = lane >> 2;
                #pragma unroll
                for (int s = 0; s < 8; s++) {
                    wmin[wid * 128 + 16 * s + rr]     = vmin[s][0];
                    wmin[wid * 128 + 16 * s + rr + 8] = vmin[s][1];
                }
            }
            __syncthreads();

            // combine: each thread owns one n-column of the pair
            {
                float m = fminf(fminf(wmin[tid], wmin[128 + tid]),
                                fminf(wmin[256 + tid], wmin[384 + tid]));
                float z2 = g_ze2[pair * 128 + tid];
                float p = 1.25f * (m + z2);
                #pragma unroll
                for (int off = 16; off > 0; off >>= 1)
                    p += __shfl_down_sync(0xFFFFFFFFu, p, off);
                if (lane == 0) red[wid] = p;
            }
            __syncthreads();
            if (tid == 0)
                g_partials[pair] = (red[0] + red[1]) + (red[2] + red[3]);
        } else {
            // ================= REC tile (128 n), 4-deep reg pipeline =================
            const int rt = sub_id(cur);
            const int b  = rt >> 6;
            const int nt = rt & 63;
            const int n  = nt * 128 + tid;
            const float* base = qp + (size_t)b * C_DIM * N_DIM + n;

            float x[4][16];
            #pragma unroll
            for (int d = 0; d < 4; d++)
                #pragma unroll
                for (int j = 0; j < 16; j++)
                    x[d][j] = base[(size_t)(16 * d + j) * N_DIM];

            float acc[8];
            #pragma unroll
            for (int j = 0; j < 8; j++) acc[j] = 0.0f;

            #pragma unroll
            for (int bt = 0; bt < 16; bt++) {
                #pragma unroll
                for (int j = 0; j < 16; j++)
                    acc[j & 7] += __expf(x[bt & 3][j]);
                if (bt < 12) {
                    #pragma unroll
                    for (int j = 0; j < 16; j++)
                        x[bt & 3][j] = base[(size_t)(16 * (bt + 4) + j) * N_DIM];
                }
            }
            float ssum = ((acc[0] + acc[1]) + (acc[2] + acc[3]))
                       + ((acc[4] + acc[5]) + (acc[6] + acc[7]));
            int t = tw[(size_t)b * N_DIM + n];
            t = min(max(t, 0), C_DIM - 1);
            float rec = __logf(ssum) - base[(size_t)t * N_DIM];

            #pragma unroll
            for (int off = 16; off > 0; off >>= 1)
                rec += __shfl_down_sync(0xFFFFFFFFu, rec, off);
            if (lane == 0) red[wid] = rec;
            __syncthreads();
            if (tid == 0)
                g_partials[N_VQ_PAIRS + rt] = (red[0] + red[1]) + (red[2] + red[3]);
        }

        // advance pipeline state
        if (curvq) pend = -1;     // cur's buffer consumed
        if (nok) { pend = next; pbuf = nb; }
        cur = next;
    }

    finalize(out);
}

// -------------------- launch --------------------
extern "C" void kernel_launch(void* const* d_in, const int* in_sizes, int n_in,
                              void* d_out, int out_size) {
    const float* ze  = (const float*)d_in[0];   // (B,Q,N)
    const float* emb = (const float*)d_in[1];   // (K,Q)
    const float* qp  = (const float*)d_in[2];   // (B,C,N)
    const int*   tw  = (const int*)d_in[3];     // (B,N) int32
    float* out = (float*)d_out;

    cudaFuncSetAttribute(fused_kernel, cudaFuncAttributeMaxDynamicSharedMemorySize,
                         SMEM_TOTAL);
    fused_kernel<<<GRID, THREADS, SMEM_TOTAL>>>(ze, emb, qp, tw, out);
}

// round 17
// speedup vs baseline: 1.2863x; 1.2863x over previous
#include <cuda_runtime.h>
#include <cuda_bf16.h>
#include <stdint.h>
#include <math.h>

#define B_DIM 8
#define Q_DIM 64
#define N_DIM 8192
#define K_DIM 512
#define C_DIM 256

#define GRID 304               // persistent CTAs, 2 per SM
#define THREADS 128
#define N_VQ_PAIRS 512         // 128 n-columns each (two 64-col tiles)
#define N_REC_TILES 512        // 128 n-columns each
#define N_WORK (N_VQ_PAIRS + N_REC_TILES)   // 1024, alternating vq/rec
#define NP N_WORK

__device__ float g_partials[NP];
__device__ int   g_arrived;
__device__ int   g_work;

// ---------------- smem layout (bytes) ----------------
#define SM_Z2    0             // 512B  (ze2 per column, 128 cols)
#define SM_E2    512           // 2048B (||emb_k||^2)
#define SM_WMIN  2560          // 2048B ([4 warps][128 n])
#define SM_RED   4608          // 32B
#define SM_ZET   4736          // 16384B (zeT[128 n][64 q] bf16, SW128 swizzled)
#define SM_EMB   21120         // 65536B (emb bf16, swizzled)
#define SMEM_TOTAL 86656       // ~85 KB -> 2 CTAs/SM

// ---------------- helpers ----------------
__device__ __forceinline__ uint32_t smem_u32(const void* p) {
    uint32_t a;
    asm("{ .reg .u64 t; cvta.to.shared.u64 t, %1; cvt.u32.u64 %0, t; }" : "=r"(a) : "l"(p));
    return a;
}

#define LDSM_X4(r0, r1, r2, r3, addr) \
    asm volatile("ldmatrix.sync.aligned.m8n8.x4.shared.b16 {%0,%1,%2,%3}, [%4];" \
                 : "=r"(r0), "=r"(r1), "=r"(r2), "=r"(r3) : "r"(addr))

// non-accumulating MMA: D = A*B (C operand = zeros in regs)
#define MMA_BF16_Z(a0, a1, a2, a3, b0, b1, c0, c1, c2, c3) \
    asm volatile("mma.sync.aligned.m16n8k16.row.col.f32.bf16.bf16.f32 " \
                 "{%0,%1,%2,%3}, {%4,%5,%6,%7}, {%8,%9}, {%10,%11,%12,%13};" \
                 : "=f"(c0), "=f"(c1), "=f"(c2), "=f"(c3) \
                 : "r"(a0), "r"(a1), "r"(a2), "r"(a3), "r"(b0), "r"(b1), \
                   "f"(0.0f), "f"(0.0f), "f"(0.0f), "f"(0.0f))

#define PREFETCH_L2(p) asm volatile("prefetch.global.L2 [%0];" :: "l"(p))

// Last-arriving block sums all partials in a FIXED order -> bit-deterministic.
__device__ __forceinline__ void finalize(float* out) {
    __shared__ float fr[4];
    __shared__ int last;
    __threadfence();
    if (threadIdx.x == 0)
        last = (atomicAdd(&g_arrived, 1) == GRID - 1);
    __syncthreads();
    if (!last) return;
    __threadfence();
    float s = 0.0f;
    for (int i = threadIdx.x; i < NP; i += THREADS)
        s += g_partials[i];
    #pragma unroll
    for (int off = 16; off > 0; off >>= 1)
        s += __shfl_down_sync(0xFFFFFFFFu, s, off);
    if ((threadIdx.x & 31) == 0) fr[threadIdx.x >> 5] = s;
    __syncthreads();
    if (threadIdx.x == 0) {
        out[0] = ((fr[0] + fr[1]) + (fr[2] + fr[3]));
        g_arrived = 0;
        g_work = 0;
    }
}

// Prefetch the next vq pair's ze data into L2 (256 x 128B lines, 2/thread).
__device__ __forceinline__ void prefetch_pair(const float* __restrict__ ze,
                                              int pair, int tid) {
    const int b  = pair >> 6;
    const int n0 = (pair & 63) << 7;
    const char* zp = (const char*)(ze + (size_t)b * Q_DIM * N_DIM + n0);
    #pragma unroll
    for (int i = 0; i < 2; i++) {
        int idx = tid * 2 + i;             // 0..255
        int q = idx >> 2, off = (idx & 3) * 128;
        PREFETCH_L2(zp + (size_t)q * N_DIM * 4 + off);
    }
}

// ==================== fused persistent kernel ====================
// 128 threads = 4 warps (256-reg budget). Per vq PAIR (128 n-cols):
// warp w owns codewords [128w,128w+128); holds ALL 8 A-sets (128 n) in
// registers; streams B ONCE per pair. All 32 MMAs per ct-group are
// INDEPENDENT (own accumulators) -> issue-limited, not latency-limited.
__global__ __launch_bounds__(THREADS, 2) void fused_kernel(
    const float* __restrict__ ze, const float* __restrict__ emb,
    const float* __restrict__ qp, const int* __restrict__ tw,
    float* __restrict__ out)
{
    extern __shared__ char smem[];
    __shared__ int ids[2];
    const uint32_t sb = smem_u32(smem);
    const int tid  = threadIdx.x;
    const int lane = tid & 31;
    const int wid  = tid >> 5;

    float* z2s  = (float*)(smem + SM_Z2);
    float* wmin = (float*)(smem + SM_WMIN);
    float* red  = (float*)(smem + SM_RED);

    // ---- one-time: emb fp32 -> bf16 swizzled smem + ||emb||^2 ----
    {
        float* e2 = (float*)(smem + SM_E2);
        #pragma unroll
        for (int i = 0; i < K_DIM / THREADS; i++) {
            int k = tid + THREADS * i;
            const float4* src = (const float4*)(emb + (size_t)k * Q_DIM);
            char* dst = smem + SM_EMB + k * 128;
            const int kx = k & 7;
            float s = 0.0f;
            #pragma unroll
            for (int j = 0; j < 8; j++) {
                float4 v0 = src[2 * j];
                float4 v1 = src[2 * j + 1];
                s = fmaf(v0.x, v0.x, s); s = fmaf(v0.y, v0.y, s);
                s = fmaf(v0.z, v0.z, s); s = fmaf(v0.w, v0.w, s);
                s = fmaf(v1.x, v1.x, s); s = fmaf(v1.y, v1.y, s);
                s = fmaf(v1.z, v1.z, s); s = fmaf(v1.w, v1.w, s);
                __nv_bfloat162 p0 = __floats2bfloat162_rn(v0.x, v0.y);
                __nv_bfloat162 p1 = __floats2bfloat162_rn(v0.z, v0.w);
                __nv_bfloat162 p2 = __floats2bfloat162_rn(v1.x, v1.y);
                __nv_bfloat162 p3 = __floats2bfloat162_rn(v1.z, v1.w);
                uint4 u;
                u.x = *(uint32_t*)&p0; u.y = *(uint32_t*)&p1;
                u.z = *(uint32_t*)&p2; u.w = *(uint32_t*)&p3;
                *(uint4*)(dst + ((j ^ kx) * 16)) = u;
            }
            e2[k] = s;
        }
    }

    const float* e2s = (const float*)(smem + SM_E2);

    // Swizzled, loop-invariant ldmatrix addresses
    uint32_t aaddr[4];
    #pragma unroll
    for (int ks = 0; ks < 4; ks++)
        aaddr[ks] = sb + SM_ZET + (uint32_t)(lane & 15) * 128u
                  + (uint32_t)((((lane >> 4) + 2 * ks) ^ (lane & 7)) * 16);
    const uint32_t baddr0 = sb + SM_EMB + (uint32_t)(128 * wid + (lane & 7)) * 128u
                          + (uint32_t)(((lane >> 3) ^ (lane & 7)) * 16);
    const uint32_t baddr1 = sb + SM_EMB + (uint32_t)(128 * wid + (lane & 7)) * 128u
                          + (uint32_t)((((lane >> 3) + 4) ^ (lane & 7)) * 16);

    if (tid == 0) ids[0] = atomicAdd(&g_work, 1);
    __syncthreads();
    int id = ids[0];
    int pr = 0;
    if (id < N_WORK && (id & 1) == 0)
        prefetch_pair(ze, id >> 1, tid);

    while (id < N_WORK) {
        if (tid == 0) ids[pr ^ 1] = atomicAdd(&g_work, 1);
        __syncthreads();                   // ids ready + smem reuse guard
        const int next = ids[pr ^ 1];
        if (next < N_WORK && (next & 1) == 0)
            prefetch_pair(ze, next >> 1, tid);

        if ((id & 1) == 0) {
            // ================= VQ pair (128 n-columns) =================
            const int pair = id >> 1;
            const int b  = pair >> 6;
            const int n0 = (pair & 63) << 7;
            const float* zp = ze + (size_t)b * Q_DIM * N_DIM + n0;

            // ---- convert: gmem fp32 (L2-prefetched) -> zeT bf16 + ze2 ----
            {
                const int c = tid;           // one column per thread (0..127)
                const float* zc = zp + c;
                const int cx = c & 7;
                float z2 = 0.0f;
                char* dstr = smem + SM_ZET + c * 128;
                #pragma unroll
                for (int h = 0; h < 8; h++) {    // 8 q per 16B chunk
                    float x0 = zc[(size_t)(8 * h + 0) * N_DIM];
                    float x1 = zc[(size_t)(8 * h + 1) * N_DIM];
                    float x2 = zc[(size_t)(8 * h + 2) * N_DIM];
                    float x3 = zc[(size_t)(8 * h + 3) * N_DIM];
                    float x4 = zc[(size_t)(8 * h + 4) * N_DIM];
                    float x5 = zc[(size_t)(8 * h + 5) * N_DIM];
                    float x6 = zc[(size_t)(8 * h + 6) * N_DIM];
                    float x7 = zc[(size_t)(8 * h + 7) * N_DIM];
                    z2 = fmaf(x0, x0, z2); z2 = fmaf(x1, x1, z2);
                    z2 = fmaf(x2, x2, z2); z2 = fmaf(x3, x3, z2);
                    z2 = fmaf(x4, x4, z2); z2 = fmaf(x5, x5, z2);
                    z2 = fmaf(x6, x6, z2); z2 = fmaf(x7, x7, z2);
                    __nv_bfloat162 p0 = __floats2bfloat162_rn(x0, x1);
                    __nv_bfloat162 p1 = __floats2bfloat162_rn(x2, x3);
                    __nv_bfloat162 p2 = __floats2bfloat162_rn(x4, x5);
                    __nv_bfloat162 p3 = __floats2bfloat162_rn(x6, x7);
                    uint4 u;
                    u.x = *(uint32_t*)&p0; u.y = *(uint32_t*)&p1;
                    u.z = *(uint32_t*)&p2; u.w = *(uint32_t*)&p3;
                    *(uint4*)(dstr + ((h ^ cx) * 16)) = u;
                }
                z2s[c] = z2;
            }
            __syncthreads();

            // ---- ALL 8 A-sets (128 n-rows) into registers (128 regs) ----
            uint32_t a[8][4][4];
            #pragma unroll
            for (int s = 0; s < 8; s++) {
                #pragma unroll
                for (int ks = 0; ks < 4; ks++)
                    LDSM_X4(a[s][ks][0], a[s][ks][1], a[s][ks][2], a[s][ks][3],
                            aaddr[ks] + (uint32_t)s * 2048u);
            }

            float vmin[8][2];
            #pragma unroll
            for (int s = 0; s < 8; s++) { vmin[s][0] = 3.4e38f; vmin[s][1] = 3.4e38f; }

            // ---- stream B once: 16 groups x (2 LDSM.x4 + 32 INDEPENDENT MMAs) ----
            #pragma unroll 2
            for (int ct = 0; ct < 16; ct++) {
                uint32_t bb[8];
                LDSM_X4(bb[0], bb[1], bb[2], bb[3], baddr0 + (uint32_t)ct * 1024u);
                LDSM_X4(bb[4], bb[5], bb[6], bb[7], baddr1 + (uint32_t)ct * 1024u);
                float2 e2 = *(const float2*)(e2s + 128 * wid + ct * 8 + 2 * (lane & 3));
                #pragma unroll
                for (int s = 0; s < 8; s++) {
                    // 4 MMAs with PRIVATE accumulators -> zero dep chains
                    float p0, p1, p2, p3, q0, q1, q2, q3;
                    float r0, r1, r2, r3, t0, t1, t2, t3;
                    MMA_BF16_Z(a[s][0][0], a[s][0][1], a[s][0][2], a[s][0][3], bb[0], bb[1], p0, p1, p2, p3);
                    MMA_BF16_Z(a[s][1][0], a[s][1][1], a[s][1][2], a[s][1][3], bb[2], bb[3], q0, q1, q2, q3);
                    MMA_BF16_Z(a[s][2][0], a[s][2][1], a[s][2][2], a[s][2][3], bb[4], bb[5], r0, r1, r2, r3);
                    MMA_BF16_Z(a[s][3][0], a[s][3][1], a[s][3][2], a[s][3][3], bb[6], bb[7], t0, t1, t2, t3);
                    float c0 = (p0 + q0) + (r0 + t0);
                    float c1 = (p1 + q1) + (r1 + t1);
                    float c2 = (p2 + q2) + (r2 + t2);
                    float c3 = (p3 + q3) + (r3 + t3);
                    vmin[s][0] = fminf(vmin[s][0],
                                       fminf(fmaf(-2.0f, c0, e2.x), fmaf(-2.0f, c1, e2.y)));
                    vmin[s][1] = fminf(vmin[s][1],
                                       fminf(fmaf(-2.0f, c2, e2.x), fmaf(-2.0f, c3, e2.y)));
                }
            }

            // min across the 4 lanes of each row-quad
            #pragma unroll
            for (int s = 0; s < 8; s++) {
                #pragma unroll
                for (int h = 0; h < 2; h++) {
                    vmin[s][h] = fminf(vmin[s][h], __shfl_xor_sync(0xFFFFFFFFu, vmin[s][h], 1));
                    vmin[s][h] = fminf(vmin[s][h], __shfl_xor_sync(0xFFFFFFFFu, vmin[s][h], 2));
                }
            }
            if ((lane & 3) == 0) {
                int rr = lane >> 2;
                #pragma unroll
                for (int s = 0; s < 8; s++) {
                    wmin[wid * 128 + 16 * s + rr]     = vmin[s][0];
                    wmin[wid * 128 + 16 * s + rr + 8] = vmin[s][1];
                }
            }
            __syncthreads();

            // combine: each thread owns one n-column of the pair
            {
                float m = fminf(fminf(wmin[tid], wmin[128 + tid]),
                                fminf(wmin[256 + tid], wmin[384 + tid]));
                float p = 1.25f * (m + z2s[tid]);
                #pragma unroll
                for (int off = 16; off > 0; off >>= 1)
                    p += __shfl_down_sync(0xFFFFFFFFu, p, off);
                if (lane == 0) red[wid] = p;
            }
            __syncthreads();
            if (tid == 0)
                g_partials[pair] = (red[0] + red[1]) + (red[2] + red[3]);
        } else {
            // ================= REC tile (128 n), 4-deep reg pipeline =================
            const int rt = id >> 1;             // 0..511
            const int b  = rt >> 6;
            const int nt = rt & 63;
            const int n  = nt * 128 + tid;
            const float* base = qp + (size_t)b * C_DIM * N_DIM + n;

            float x[4][16];
            #pragma unroll
            for (int d = 0; d < 4; d++)
                #pragma unroll
                for (int j = 0; j < 16; j++)
                    x[d][j] = base[(size_t)(16 * d + j) * N_DIM];

            float acc[8];
            #pragma unroll
            for (int j = 0; j < 8; j++) acc[j] = 0.0f;

            #pragma unroll
            for (int bt = 0; bt < 16; bt++) {
                #pragma unroll
                for (int j = 0; j < 16; j++)
                    acc[j & 7] += __expf(x[bt & 3][j]);
                if (bt < 12) {
                    #pragma unroll
                    for (int j = 0; j < 16; j++)
                        x[bt & 3][j] = base[(size_t)(16 * (bt + 4) + j) * N_DIM];
                }
            }
            float ssum = ((acc[0] + acc[1]) + (acc[2] + acc[3]))
                       + ((acc[4] + acc[5]) + (acc[6] + acc[7]));
            int t = tw[(size_t)b * N_DIM + n];
            t = min(max(t, 0), C_DIM - 1);
            float rec = __logf(ssum) - base[(size_t)t * N_DIM];

            #pragma unroll
            for (int off = 16; off > 0; off >>= 1)
                rec += __shfl_down_sync(0xFFFFFFFFu, rec, off);
            if (lane == 0) red[wid] = rec;
            __syncthreads();
            if (tid == 0)
                g_partials[N_VQ_PAIRS + rt] = (red[0] + red[1]) + (red[2] + red[3]);
        }

        id = next;
        pr ^= 1;
    }

    finalize(out);
}

// -------------------- launch --------------------
extern "C" void kernel_launch(void* const* d_in, const int* in_sizes, int n_in,
                              void* d_out, int out_size) {
    const float* ze  = (const float*)d_in[0];   // (B,Q,N)
    const float* emb = (const float*)d_in[1];   // (K,Q)
    const float* qp  = (const float*)d_in[2];   // (B,C,N)
    const int*   tw  = (const int*)d_in[3];     // (B,N) int32
    float* out = (float*)d_out;

    cudaFuncSetAttribute(fused_kernel, cudaFuncAttributeMaxDynamicSharedMemorySize,
                         SMEM_TOTAL);
    fused_kernel<<<GRID, THREADS, SMEM_TOTAL>>>(ze, emb, qp, tw, out);
}